// round 1
// baseline (speedup 1.0000x reference)
#include <cuda_runtime.h>

#define NV0 64
#define NV1 128
#define NV  8192   // V0*V1
#define NC  128

// Scratch (device globals — no allocations allowed in kernel_launch)
__device__ float g_xw[NV * NC];   // mass-weighted input
__device__ float g_y[NV * NC];    // coef * x_spec

// ---------------------------------------------------------------------------
// prep: xw[v,c] = x[v,c] * mass[v]
// ---------------------------------------------------------------------------
__global__ void __launch_bounds__(256) prep_kernel(const float* __restrict__ x,
                                                   const float* __restrict__ mass,
                                                   float* __restrict__ xw) {
    int idx = blockIdx.x * 256 + threadIdx.x;   // < NV*NC guaranteed by grid
    xw[idx] = x[idx] * mass[idx >> 7];          // NC == 128
}

// ---------------------------------------------------------------------------
// SGEMM: C[m,n] = sum_k Aop[m,k] * B[k,n]
//   TRANS_A = 1: Aop[m,k] = A[k*NV + m]   (evecs^T, GEMM1)
//   TRANS_A = 0: Aop[m,k] = A[m*NV + k]   (evecs,   GEMM2)
//   APPLY_COEF = 1: multiply output by exp(-(evals0[m/128]*t0[n] + evals1[m%128]*t1[n]))
// Tiles: BM=64, BN=128, BK=16; 256 threads; each thread 4(M) x 8(N).
// Grid: NV/BM = 128 blocks -> one wave on 148 SMs.
// ---------------------------------------------------------------------------
template <int TRANS_A, int APPLY_COEF>
__global__ void __launch_bounds__(256) sgemm_kernel(
    const float* __restrict__ A,
    const float* __restrict__ B,
    float* __restrict__ Cmat,
    const float* __restrict__ evals0,
    const float* __restrict__ evals1,
    const float* __restrict__ dt)   // [2, NC]
{
    constexpr int BM = 64, BN = 128, BK = 16;
    __shared__ float As[BK][BM + 4];   // +4 pad to soften transpose-store conflicts
    __shared__ float Bs[BK][BN];

    const int tid = threadIdx.x;
    const int m0  = blockIdx.x * BM;
    const int tx  = tid & 15;    // N group: 8 cols each
    const int ty  = tid >> 4;    // M group: 4 rows each

    float acc[4][8];
#pragma unroll
    for (int i = 0; i < 4; i++)
#pragma unroll
        for (int j = 0; j < 8; j++) acc[i][j] = 0.0f;

    for (int k0 = 0; k0 < NV; k0 += BK) {
        // ---- load A tile ----
        if (TRANS_A) {
            // A[k, m] with m contiguous: one float4 per thread, coalesced.
            int kk = tid >> 4;          // 0..15
            int mm = (tid & 15) * 4;    // 0..60
            float4 a4 = *(const float4*)&A[(size_t)(k0 + kk) * NV + m0 + mm];
            As[kk][mm + 0] = a4.x;
            As[kk][mm + 1] = a4.y;
            As[kk][mm + 2] = a4.z;
            As[kk][mm + 3] = a4.w;
        } else {
            // A[m, k] row-major: float4 along k, transpose into As.
            int mm = tid >> 2;          // 0..63
            int kk = (tid & 3) * 4;     // 0..12
            float4 a4 = *(const float4*)&A[(size_t)(m0 + mm) * NV + k0 + kk];
            As[kk + 0][mm] = a4.x;
            As[kk + 1][mm] = a4.y;
            As[kk + 2][mm] = a4.z;
            As[kk + 3][mm] = a4.w;
        }
        // ---- load B tile: rows k0..k0+15, all 128 cols (contiguous 2048 floats) ----
        {
            const float4* Bg = (const float4*)&B[(size_t)k0 * NC];
            float4 b0 = Bg[tid];
            float4 b1 = Bg[tid + 256];
            ((float4*)&Bs[0][0])[tid] = b0;
            ((float4*)&Bs[0][0])[tid + 256] = b1;
        }
        __syncthreads();

        // ---- compute ----
#pragma unroll
        for (int kk = 0; kk < BK; kk++) {
            float a0 = As[kk][ty * 4 + 0];
            float a1 = As[kk][ty * 4 + 1];
            float a2 = As[kk][ty * 4 + 2];
            float a3 = As[kk][ty * 4 + 3];
            float4 b0 = *(const float4*)&Bs[kk][tx * 8];
            float4 b1 = *(const float4*)&Bs[kk][tx * 8 + 4];
            float bv[8] = {b0.x, b0.y, b0.z, b0.w, b1.x, b1.y, b1.z, b1.w};
#pragma unroll
            for (int j = 0; j < 8; j++) {
                acc[0][j] += a0 * bv[j];
                acc[1][j] += a1 * bv[j];
                acc[2][j] += a2 * bv[j];
                acc[3][j] += a3 * bv[j];
            }
        }
        __syncthreads();
    }

    // ---- epilogue ----
#pragma unroll
    for (int i = 0; i < 4; i++) {
        int gm = m0 + ty * 4 + i;
        float e0 = 0.0f, e1 = 0.0f;
        if (APPLY_COEF) {
            e0 = evals0[gm >> 7];    // i0 = gm / NV1 (NV1 == 128)
            e1 = evals1[gm & 127];   // i1 = gm % NV1
        }
#pragma unroll
        for (int j = 0; j < 8; j++) {
            int gn = tx * 8 + j;
            float v = acc[i][j];
            if (APPLY_COEF) {
                float t0 = dt[gn];
                float t1 = dt[NC + gn];
                v *= __expf(-(e0 * t0 + e1 * t1));
            }
            Cmat[(size_t)gm * NC + gn] = v;
        }
    }
}

// ---------------------------------------------------------------------------
// Inputs (metadata order): 0:x[V,C] 1:edge_index 2:L 3:mass[V] 4:evals0[64]
//                          5:evals1[128] 6:evecs[V,V] 7:diffusion_time[2,C]
// Output: x_diffuse [V, C] float32
// ---------------------------------------------------------------------------
extern "C" void kernel_launch(void* const* d_in, const int* in_sizes, int n_in,
                              void* d_out, int out_size) {
    const float* x      = (const float*)d_in[0];
    const float* mass   = (const float*)d_in[3];
    const float* evals0 = (const float*)d_in[4];
    const float* evals1 = (const float*)d_in[5];
    const float* evecs  = (const float*)d_in[6];
    const float* dt     = (const float*)d_in[7];
    float* out          = (float*)d_out;

    float *xw = nullptr, *y = nullptr;
    cudaGetSymbolAddress((void**)&xw, g_xw);
    cudaGetSymbolAddress((void**)&y,  g_y);

    // xw = x * mass
    prep_kernel<<<(NV * NC) / 256, 256>>>(x, mass, xw);
    // y = coef .* (evecs^T @ xw)
    sgemm_kernel<1, 1><<<NV / 64, 256>>>(evecs, xw, y, evals0, evals1, dt);
    // out = evecs @ y
    sgemm_kernel<0, 0><<<NV / 64, 256>>>(evecs, y, out, evals0, evals1, dt);
}

// round 3
// speedup vs baseline: 4.3035x; 4.3035x over previous
#include <cuda_runtime.h>
#include <cuda_bf16.h>
#include <cstdint>

#define NV 8192
#define NC 128

// -------------------- device scratch (no allocs allowed) --------------------
__device__ float g_y[NV * NC];       // GEMM1 output (coef * x_spec), fp32
__device__ float g_E0[64 * NC];      // exp(-evals0[i] * t0[c])
__device__ float g_E1[128 * NC];     // exp(-evals1[j] * t1[c])

// -------------------- coef tables -------------------------------------------
__global__ void coef_kernel(const float* __restrict__ ev0,
                            const float* __restrict__ ev1,
                            const float* __restrict__ dt) {
    int c = threadIdx.x;
    float t0 = dt[c], t1 = dt[NC + c];
    for (int i = 0; i < 64; i++)  g_E0[i * NC + c] = __expf(-ev0[i] * t0);
    for (int j = 0; j < 128; j++) g_E1[j * NC + c] = __expf(-ev1[j] * t1);
}

// -------------------- mma.sync helpers (sm_80+ family-portable) -------------
__device__ __forceinline__ void ldsm4(uint32_t* r, uint32_t addr) {
    asm volatile("ldmatrix.sync.aligned.m8n8.x4.shared.b16 {%0,%1,%2,%3}, [%4];"
                 : "=r"(r[0]), "=r"(r[1]), "=r"(r[2]), "=r"(r[3]) : "r"(addr));
}
__device__ __forceinline__ void ldsm4t(uint32_t* r, uint32_t addr) {
    asm volatile("ldmatrix.sync.aligned.m8n8.x4.trans.shared.b16 {%0,%1,%2,%3}, [%4];"
                 : "=r"(r[0]), "=r"(r[1]), "=r"(r[2]), "=r"(r[3]) : "r"(addr));
}
__device__ __forceinline__ void mma16816(float* d, const uint32_t* a, const uint32_t* b) {
    asm volatile("mma.sync.aligned.m16n8k16.row.col.f32.bf16.bf16.f32 "
                 "{%0,%1,%2,%3}, {%4,%5,%6,%7}, {%8,%9}, {%0,%1,%2,%3};"
                 : "+f"(d[0]), "+f"(d[1]), "+f"(d[2]), "+f"(d[3])
                 : "r"(a[0]), "r"(a[1]), "r"(a[2]), "r"(a[3]),
                   "r"(b[0]), "r"(b[1]));
}

// -------------------- GEMM config --------------------------------------------
#define BM 64
#define BN 128
#define BK 64
#define APAD 72                      // halves per A row (stride 144B, mod128=16)
#define BPAD 136                     // halves per B row (stride 272B, mod128=16)
#define A_HALVES (BK * APAD)         // 4608 halves (tile stored [row][col], 64x64 used)
#define B_HALVES (BK * BPAD)         // 8704
#define A_BYTES  (A_HALVES * 2)      // 9216
#define B_BYTES  (B_HALVES * 2)      // 17408
#define STAGE_BYTES (2 * A_BYTES + 2 * B_BYTES)   // Ahi,Alo,Bhi,Blo = 53248
#define SMEM_BYTES  (2 * STAGE_BYTES)             // 106496

// C[m,n] = sum_k Aop[m,k]*B[k,n], bf16 hi/lo split (AhBh + AhBl + AlBh), fp32 I/O.
// TRANS_A=1: Aop[m,k]=A[k*NV+m] (Eᵀ), B multiplied by mass[k]; EPI=1 applies coef.
// TRANS_A=0: Aop[m,k]=A[m*NV+k] (E).
template <int TRANS_A, int EPI>
__global__ void __launch_bounds__(256, 1)
gemm_kernel(const float* __restrict__ A, const float* __restrict__ B,
            const float* __restrict__ mass, float* __restrict__ C,
            const float* __restrict__ E0, const float* __restrict__ E1)
{
    extern __shared__ __nv_bfloat16 sm[];
    const uint32_t smbase = (uint32_t)__cvta_generic_to_shared(sm);
    const int tid  = threadIdx.x;
    const int lane = tid & 31, wid = tid >> 5;
    const int wm   = wid >> 2, wn = wid & 3;     // 2 x 4 warp grid
    const int m0   = blockIdx.x * BM;

    float4 ra[4];
    float4 rb[8];
    float  rmass[8];

    // ---- global loads (fp32, coalesced) into regs ----
    auto ldg_tile = [&](int kt) {
        const int k0 = kt * BK;
#pragma unroll
        for (int i = 0; i < 4; i++) {
            int idx = i * 256 + tid;
            int r = idx >> 4, c4 = idx & 15;
            int grow = (TRANS_A ? k0 : m0) + r;
            int gcol = (TRANS_A ? m0 : k0) + c4 * 4;
            ra[i] = *(const float4*)&A[(size_t)grow * NV + gcol];
        }
#pragma unroll
        for (int i = 0; i < 8; i++) {
            int idx = i * 256 + tid;
            int r = idx >> 5, c4 = idx & 31;
            rb[i] = *(const float4*)&B[(size_t)(k0 + r) * NC + c4 * 4];
            if (TRANS_A) rmass[i] = __ldg(&mass[k0 + r]);
        }
    };

    // ---- regs -> smem with in-register fp32 -> bf16 hi/lo split ----
    auto sts_tile = [&](int s) {
        __nv_bfloat16* Ah = sm + (size_t)s * (STAGE_BYTES / 2);
        __nv_bfloat16* Al = Ah + A_HALVES;
        __nv_bfloat16* Bh = Al + A_HALVES;
        __nv_bfloat16* Bl = Bh + B_HALVES;
#pragma unroll
        for (int i = 0; i < 4; i++) {
            int idx = i * 256 + tid;
            int r = idx >> 4, c4 = idx & 15;
            float v[4] = {ra[i].x, ra[i].y, ra[i].z, ra[i].w};
            __nv_bfloat16 h[4], l[4];
#pragma unroll
            for (int j = 0; j < 4; j++) {
                h[j] = __float2bfloat16(v[j]);
                l[j] = __float2bfloat16(v[j] - __bfloat162float(h[j]));
            }
            int off = r * APAD + c4 * 4;
            *(__nv_bfloat162*)&Ah[off]     = {h[0], h[1]};
            *(__nv_bfloat162*)&Ah[off + 2] = {h[2], h[3]};
            *(__nv_bfloat162*)&Al[off]     = {l[0], l[1]};
            *(__nv_bfloat162*)&Al[off + 2] = {l[2], l[3]};
        }
#pragma unroll
        for (int i = 0; i < 8; i++) {
            int idx = i * 256 + tid;
            int r = idx >> 5, c4 = idx & 31;
            float v[4] = {rb[i].x, rb[i].y, rb[i].z, rb[i].w};
            __nv_bfloat16 h[4], l[4];
#pragma unroll
            for (int j = 0; j < 4; j++) {
                float val = TRANS_A ? v[j] * rmass[i] : v[j];
                h[j] = __float2bfloat16(val);
                l[j] = __float2bfloat16(val - __bfloat162float(h[j]));
            }
            int off = r * BPAD + c4 * 4;
            *(__nv_bfloat162*)&Bh[off]     = {h[0], h[1]};
            *(__nv_bfloat162*)&Bh[off + 2] = {h[2], h[3]};
            *(__nv_bfloat162*)&Bl[off]     = {l[0], l[1]};
            *(__nv_bfloat162*)&Bl[off + 2] = {l[2], l[3]};
        }
    };

    float acc[2][4][4];
#pragma unroll
    for (int a = 0; a < 2; a++)
#pragma unroll
        for (int b = 0; b < 4; b++)
#pragma unroll
            for (int q = 0; q < 4; q++) acc[a][b][q] = 0.0f;

    // ---- compute one smem stage (4 k-steps of 16) ----
    auto compute = [&](int s) {
        const uint32_t Ahb = smbase + s * STAGE_BYTES;
        const uint32_t Bhb = Ahb + 2 * A_BYTES;
#pragma unroll
        for (int ks = 0; ks < 4; ks++) {
            uint32_t ah[2][4], al[2][4], bh[2][4], bl[2][4];
#pragma unroll
            for (int mi = 0; mi < 2; mi++) {
                uint32_t addr;
                if (TRANS_A) {
                    int krow = ks * 16 + (lane & 7) + ((lane >> 4) << 3);
                    int mcol = wm * 32 + mi * 16 + (lane & 8);
                    addr = Ahb + (uint32_t)(krow * APAD + mcol) * 2;
                    ldsm4t(ah[mi], addr);
                    ldsm4t(al[mi], addr + A_BYTES);
                } else {
                    int mrow = wm * 32 + mi * 16 + (lane & 15);
                    int kcol = ks * 16 + ((lane >> 4) << 3);
                    addr = Ahb + (uint32_t)(mrow * APAD + kcol) * 2;
                    ldsm4(ah[mi], addr);
                    ldsm4(al[mi], addr + A_BYTES);
                }
            }
#pragma unroll
            for (int nj2 = 0; nj2 < 2; nj2++) {
                int krow = ks * 16 + (lane & 15);
                int ncol = wn * 32 + nj2 * 16 + ((lane >> 4) << 3);
                uint32_t addr = Bhb + (uint32_t)(krow * BPAD + ncol) * 2;
                ldsm4t(bh[nj2], addr);
                ldsm4t(bl[nj2], addr + B_BYTES);
            }
#pragma unroll
            for (int mi = 0; mi < 2; mi++)
#pragma unroll
                for (int nj = 0; nj < 4; nj++) {
                    const uint32_t* bhp = &bh[nj >> 1][(nj & 1) * 2];
                    const uint32_t* blp = &bl[nj >> 1][(nj & 1) * 2];
                    mma16816(acc[mi][nj], ah[mi], bhp);
                    mma16816(acc[mi][nj], ah[mi], blp);
                    mma16816(acc[mi][nj], al[mi], bhp);
                }
        }
    };

    // ---- main loop: 2-stage double buffer ----
    ldg_tile(0);
    sts_tile(0);
    __syncthreads();
    const int NIT = NV / BK;   // 128
#pragma unroll 1
    for (int kt = 0; kt < NIT; kt++) {
        if (kt + 1 < NIT) ldg_tile(kt + 1);
        compute(kt & 1);
        __syncthreads();
        if (kt + 1 < NIT) {
            sts_tile((kt + 1) & 1);
            __syncthreads();
        }
    }

    // ---- epilogue ----
#pragma unroll
    for (int mi = 0; mi < 2; mi++) {
#pragma unroll
        for (int q = 0; q < 2; q++) {
            int gm = m0 + wm * 32 + mi * 16 + (lane >> 2) + q * 8;
            int i0 = gm >> 7, i1 = gm & 127;
#pragma unroll
            for (int nj = 0; nj < 4; nj++) {
                int gn = wn * 32 + nj * 8 + (lane & 3) * 2;
                float v0 = acc[mi][nj][q * 2 + 0];
                float v1 = acc[mi][nj][q * 2 + 1];
                if (EPI) {
                    v0 *= E0[i0 * NC + gn]     * E1[i1 * NC + gn];
                    v1 *= E0[i0 * NC + gn + 1] * E1[i1 * NC + gn + 1];
                }
                *(float2*)&C[(size_t)gm * NC + gn] = make_float2(v0, v1);
            }
        }
    }
}

// -------------------- launch --------------------------------------------------
// Inputs: 0:x[V,C] 1:edge_index 2:L 3:mass[V] 4:evals0[64] 5:evals1[128]
//         6:evecs[V,V] 7:diffusion_time[2,C]   Output: [V,C] fp32
extern "C" void kernel_launch(void* const* d_in, const int* in_sizes, int n_in,
                              void* d_out, int out_size) {
    const float* x      = (const float*)d_in[0];
    const float* mass   = (const float*)d_in[3];
    const float* evals0 = (const float*)d_in[4];
    const float* evals1 = (const float*)d_in[5];
    const float* evecs  = (const float*)d_in[6];
    const float* dt     = (const float*)d_in[7];
    float* out          = (float*)d_out;

    float *y, *E0, *E1;
    cudaGetSymbolAddress((void**)&y,  g_y);
    cudaGetSymbolAddress((void**)&E0, g_E0);
    cudaGetSymbolAddress((void**)&E1, g_E1);

    cudaFuncSetAttribute(gemm_kernel<1, 1>, cudaFuncAttributeMaxDynamicSharedMemorySize, SMEM_BYTES);
    cudaFuncSetAttribute(gemm_kernel<0, 0>, cudaFuncAttributeMaxDynamicSharedMemorySize, SMEM_BYTES);

    coef_kernel<<<1, 128>>>(evals0, evals1, dt);
    // GEMM1: y = coef .* (Eᵀ @ (x * mass))
    gemm_kernel<1, 1><<<NV / BM, 256, SMEM_BYTES>>>(evecs, x, mass, y, E0, E1);
    // GEMM2: out = E @ y
    gemm_kernel<0, 0><<<NV / BM, 256, SMEM_BYTES>>>(evecs, y, nullptr, out, nullptr, nullptr);
}

// round 4
// speedup vs baseline: 4.7041x; 1.0931x over previous
#include <cuda_runtime.h>
#include <cuda_bf16.h>
#include <cstdint>

#define NV 8192
#define NC 128

// -------------------- device scratch (no allocs allowed) --------------------
__device__ __nv_bfloat16 g_Ehi[(size_t)NV * NV];   // 128 MB
__device__ __nv_bfloat16 g_Elo[(size_t)NV * NV];   // 128 MB
__device__ __nv_bfloat16 g_xh[NV * NC];
__device__ __nv_bfloat16 g_xl[NV * NC];
__device__ __nv_bfloat16 g_yh[NV * NC];
__device__ __nv_bfloat16 g_yl[NV * NC];
__device__ float g_E0[64 * NC];
__device__ float g_E1[128 * NC];

// -------------------- small kernels ------------------------------------------
__global__ void coef_kernel(const float* __restrict__ ev0,
                            const float* __restrict__ ev1,
                            const float* __restrict__ dt) {
    int c = threadIdx.x;
    int b = blockIdx.x;
    if (b < 64) g_E0[b * NC + c] = __expf(-ev0[b] * dt[c]);
    else        g_E1[(b - 64) * NC + c] = __expf(-ev1[b - 64] * dt[NC + c]);
}

__device__ __forceinline__ uint32_t pack_bf2(__nv_bfloat16 a, __nv_bfloat16 b) {
    __nv_bfloat162 p{a, b};
    return *(uint32_t*)&p;
}

// evecs fp32 -> bf16 hi/lo (row-major only; ldmatrix.trans provides E^T)
__global__ void __launch_bounds__(256) convE_kernel(const float4* __restrict__ E4,
                                                    uint2* __restrict__ Eh,
                                                    uint2* __restrict__ El) {
    const size_t N4 = (size_t)NV * NV / 4;
    for (size_t idx = (size_t)blockIdx.x * 256 + threadIdx.x; idx < N4;
         idx += (size_t)gridDim.x * 256) {
        float4 v = E4[idx];
        __nv_bfloat16 h0 = __float2bfloat16(v.x), h1 = __float2bfloat16(v.y);
        __nv_bfloat16 h2 = __float2bfloat16(v.z), h3 = __float2bfloat16(v.w);
        __nv_bfloat16 l0 = __float2bfloat16(v.x - __bfloat162float(h0));
        __nv_bfloat16 l1 = __float2bfloat16(v.y - __bfloat162float(h1));
        __nv_bfloat16 l2 = __float2bfloat16(v.z - __bfloat162float(h2));
        __nv_bfloat16 l3 = __float2bfloat16(v.w - __bfloat162float(h3));
        Eh[idx] = make_uint2(pack_bf2(h0, h1), pack_bf2(h2, h3));
        El[idx] = make_uint2(pack_bf2(l0, l1), pack_bf2(l2, l3));
    }
}

// xw = x * mass, split hi/lo (layout [V, C] row-major, same as x)
__global__ void __launch_bounds__(256) prepx_kernel(const float4* __restrict__ x4,
                                                    const float* __restrict__ mass,
                                                    uint2* __restrict__ xh,
                                                    uint2* __restrict__ xl) {
    int idx = blockIdx.x * 256 + threadIdx.x;   // grid covers NV*NC/4 exactly
    float m = mass[(idx * 4) >> 7];
    float4 v = x4[idx];
    float a = v.x * m, b = v.y * m, c = v.z * m, d = v.w * m;
    __nv_bfloat16 h0 = __float2bfloat16(a), h1 = __float2bfloat16(b);
    __nv_bfloat16 h2 = __float2bfloat16(c), h3 = __float2bfloat16(d);
    __nv_bfloat16 l0 = __float2bfloat16(a - __bfloat162float(h0));
    __nv_bfloat16 l1 = __float2bfloat16(b - __bfloat162float(h1));
    __nv_bfloat16 l2 = __float2bfloat16(c - __bfloat162float(h2));
    __nv_bfloat16 l3 = __float2bfloat16(d - __bfloat162float(h3));
    xh[idx] = make_uint2(pack_bf2(h0, h1), pack_bf2(h2, h3));
    xl[idx] = make_uint2(pack_bf2(l0, l1), pack_bf2(l2, l3));
}

// -------------------- mma.sync helpers ----------------------------------------
__device__ __forceinline__ void ldsm4(uint32_t* r, uint32_t addr) {
    asm volatile("ldmatrix.sync.aligned.m8n8.x4.shared.b16 {%0,%1,%2,%3}, [%4];"
                 : "=r"(r[0]), "=r"(r[1]), "=r"(r[2]), "=r"(r[3]) : "r"(addr));
}
__device__ __forceinline__ void ldsm4t(uint32_t* r, uint32_t addr) {
    asm volatile("ldmatrix.sync.aligned.m8n8.x4.trans.shared.b16 {%0,%1,%2,%3}, [%4];"
                 : "=r"(r[0]), "=r"(r[1]), "=r"(r[2]), "=r"(r[3]) : "r"(addr));
}
__device__ __forceinline__ void mma16816(float* d, const uint32_t* a, const uint32_t* b) {
    asm volatile("mma.sync.aligned.m16n8k16.row.col.f32.bf16.bf16.f32 "
                 "{%0,%1,%2,%3}, {%4,%5,%6,%7}, {%8,%9}, {%0,%1,%2,%3};"
                 : "+f"(d[0]), "+f"(d[1]), "+f"(d[2]), "+f"(d[3])
                 : "r"(a[0]), "r"(a[1]), "r"(a[2]), "r"(a[3]),
                   "r"(b[0]), "r"(b[1]));
}
#define CP16(dst, src) \
    asm volatile("cp.async.cg.shared.global [%0], [%1], 16;" :: "r"(dst), "l"(src) : "memory")

// -------------------- GEMM config ----------------------------------------------
#define BM 64
#define BN 128
#define BK 64
#define APAD 72                       // halves/row: 144 B stride, mod128=16, 16B-aligned
#define BPAD 136                      // 272 B stride
#define A_HALVES (BK * APAD)          // 4608
#define B_HALVES (BK * BPAD)          // 8704
#define A_BYTES  (A_HALVES * 2)       // 9216
#define B_BYTES  (B_HALVES * 2)       // 17408
#define STAGE_BYTES (2 * A_BYTES + 2 * B_BYTES)   // 53248
#define NSTAGE 3
#define SMEM_BYTES (NSTAGE * STAGE_BYTES)         // 159744

// C[m,n] = sum_k Aop[m,k]*B[k,n]; A given as bf16 hi/lo (row-major E).
// TRANS_A=1: Aop[m,k] = E[k,m] (ldmatrix.trans absorbs it). 3-term split MMA.
// EPI=1: multiply by coef, write y hi/lo bf16. EPI=0: write fp32.
template <int TRANS_A, int EPI>
__global__ void __launch_bounds__(256, 1)
gemm_kernel(const __nv_bfloat16* __restrict__ Ahi, const __nv_bfloat16* __restrict__ Alo,
            const __nv_bfloat16* __restrict__ Bhi, const __nv_bfloat16* __restrict__ Blo,
            float* __restrict__ C,
            __nv_bfloat16* __restrict__ yhi, __nv_bfloat16* __restrict__ ylo,
            const float* __restrict__ E0, const float* __restrict__ E1)
{
    extern __shared__ __nv_bfloat16 sm[];
    const uint32_t smbase = (uint32_t)__cvta_generic_to_shared(sm);
    const int tid  = threadIdx.x;
    const int lane = tid & 31, wid = tid >> 5;
    const int wm   = wid >> 2, wn = wid & 3;      // 2 x 4 warp grid (32x32 warp tiles)
    const int m0   = blockIdx.x * BM;

    auto issue = [&](int kt, int s) {
        const int k0 = kt * BK;
        const uint32_t sb = smbase + s * STAGE_BYTES;
#pragma unroll
        for (int i = 0; i < 2; i++) {               // A hi+lo: 512 chunks each
            int idx = i * 256 + tid;
            int r = idx >> 3, q = idx & 7;
            size_t ga = TRANS_A ? (size_t)(k0 + r) * NV + m0 + q * 8
                                : (size_t)(m0 + r) * NV + k0 + q * 8;
            uint32_t so = sb + (uint32_t)(r * APAD + q * 8) * 2;
            CP16(so, (const void*)(Ahi + ga));
            CP16(so + A_BYTES, (const void*)(Alo + ga));
        }
#pragma unroll
        for (int i = 0; i < 4; i++) {               // B hi+lo: 1024 chunks each
            int idx = i * 256 + tid;
            int r = idx >> 4, q = idx & 15;
            size_t gb = (size_t)(k0 + r) * NC + q * 8;
            uint32_t so = sb + 2 * A_BYTES + (uint32_t)(r * BPAD + q * 8) * 2;
            CP16(so, (const void*)(Bhi + gb));
            CP16(so + B_BYTES, (const void*)(Blo + gb));
        }
        asm volatile("cp.async.commit_group;" ::: "memory");
    };

    float acc[2][4][4];
#pragma unroll
    for (int a = 0; a < 2; a++)
#pragma unroll
        for (int b = 0; b < 4; b++)
#pragma unroll
            for (int q = 0; q < 4; q++) acc[a][b][q] = 0.0f;

    auto compute = [&](int s) {
        const uint32_t Ahb = smbase + s * STAGE_BYTES;
        const uint32_t Bhb = Ahb + 2 * A_BYTES;
#pragma unroll
        for (int ks = 0; ks < 4; ks++) {
            uint32_t ah[2][4], al[2][4], bh[2][4], bl[2][4];
#pragma unroll
            for (int mi = 0; mi < 2; mi++) {
                uint32_t addr;
                if (TRANS_A) {
                    int krow = ks * 16 + (lane & 7) + ((lane >> 4) << 3);
                    int mcol = wm * 32 + mi * 16 + (lane & 8);
                    addr = Ahb + (uint32_t)(krow * APAD + mcol) * 2;
                    ldsm4t(ah[mi], addr);
                    ldsm4t(al[mi], addr + A_BYTES);
                } else {
                    int mrow = wm * 32 + mi * 16 + (lane & 15);
                    int kcol = ks * 16 + ((lane >> 4) << 3);
                    addr = Ahb + (uint32_t)(mrow * APAD + kcol) * 2;
                    ldsm4(ah[mi], addr);
                    ldsm4(al[mi], addr + A_BYTES);
                }
            }
#pragma unroll
            for (int nj2 = 0; nj2 < 2; nj2++) {
                int krow = ks * 16 + (lane & 15);
                int ncol = wn * 32 + nj2 * 16 + ((lane >> 4) << 3);
                uint32_t addr = Bhb + (uint32_t)(krow * BPAD + ncol) * 2;
                ldsm4t(bh[nj2], addr);
                ldsm4t(bl[nj2], addr + B_BYTES);
            }
#pragma unroll
            for (int mi = 0; mi < 2; mi++)
#pragma unroll
                for (int nj = 0; nj < 4; nj++) {
                    const uint32_t* bhp = &bh[nj >> 1][(nj & 1) * 2];
                    const uint32_t* blp = &bl[nj >> 1][(nj & 1) * 2];
                    mma16816(acc[mi][nj], ah[mi], bhp);
                    mma16816(acc[mi][nj], ah[mi], blp);
                    mma16816(acc[mi][nj], al[mi], bhp);
                }
        }
    };

    const int NIT = NV / BK;   // 128
    issue(0, 0);
    issue(1, 1);
#pragma unroll 1
    for (int kt = 0; kt < NIT; kt++) {
        if (kt < NIT - 1) asm volatile("cp.async.wait_group 1;" ::: "memory");
        else              asm volatile("cp.async.wait_group 0;" ::: "memory");
        __syncthreads();
        compute(kt % NSTAGE);
        if (kt + 2 < NIT) issue(kt + 2, (kt + 2) % NSTAGE);
    }

    // ---- epilogue ----
#pragma unroll
    for (int mi = 0; mi < 2; mi++) {
#pragma unroll
        for (int q = 0; q < 2; q++) {
            int gm = m0 + wm * 32 + mi * 16 + (lane >> 2) + q * 8;
            int i0 = gm >> 7, i1 = gm & 127;
#pragma unroll
            for (int nj = 0; nj < 4; nj++) {
                int gn = wn * 32 + nj * 8 + (lane & 3) * 2;
                float v0 = acc[mi][nj][q * 2 + 0];
                float v1 = acc[mi][nj][q * 2 + 1];
                if (EPI) {
                    v0 *= E0[i0 * NC + gn]     * E1[i1 * NC + gn];
                    v1 *= E0[i0 * NC + gn + 1] * E1[i1 * NC + gn + 1];
                    __nv_bfloat16 h0 = __float2bfloat16(v0);
                    __nv_bfloat16 h1 = __float2bfloat16(v1);
                    __nv_bfloat16 l0 = __float2bfloat16(v0 - __bfloat162float(h0));
                    __nv_bfloat16 l1 = __float2bfloat16(v1 - __bfloat162float(h1));
                    *(uint32_t*)&yhi[(size_t)gm * NC + gn] = pack_bf2(h0, h1);
                    *(uint32_t*)&ylo[(size_t)gm * NC + gn] = pack_bf2(l0, l1);
                } else {
                    *(float2*)&C[(size_t)gm * NC + gn] = make_float2(v0, v1);
                }
            }
        }
    }
}

// -------------------- launch -----------------------------------------------------
// Inputs: 0:x[V,C] 1:edge_index 2:L 3:mass[V] 4:evals0[64] 5:evals1[128]
//         6:evecs[V,V] 7:diffusion_time[2,C]   Output: [V,C] fp32
extern "C" void kernel_launch(void* const* d_in, const int* in_sizes, int n_in,
                              void* d_out, int out_size) {
    const float* x      = (const float*)d_in[0];
    const float* mass   = (const float*)d_in[3];
    const float* evals0 = (const float*)d_in[4];
    const float* evals1 = (const float*)d_in[5];
    const float* evecs  = (const float*)d_in[6];
    const float* dt     = (const float*)d_in[7];
    float* out          = (float*)d_out;

    __nv_bfloat16 *Eh, *El, *xh, *xl, *yh, *yl;
    float *E0, *E1;
    cudaGetSymbolAddress((void**)&Eh, g_Ehi);
    cudaGetSymbolAddress((void**)&El, g_Elo);
    cudaGetSymbolAddress((void**)&xh, g_xh);
    cudaGetSymbolAddress((void**)&xl, g_xl);
    cudaGetSymbolAddress((void**)&yh, g_yh);
    cudaGetSymbolAddress((void**)&yl, g_yl);
    cudaGetSymbolAddress((void**)&E0, g_E0);
    cudaGetSymbolAddress((void**)&E1, g_E1);

    cudaFuncSetAttribute(gemm_kernel<1, 1>, cudaFuncAttributeMaxDynamicSharedMemorySize, SMEM_BYTES);
    cudaFuncSetAttribute(gemm_kernel<0, 0>, cudaFuncAttributeMaxDynamicSharedMemorySize, SMEM_BYTES);

    coef_kernel<<<192, 128>>>(evals0, evals1, dt);
    convE_kernel<<<2368, 256>>>((const float4*)evecs, (uint2*)Eh, (uint2*)El);
    prepx_kernel<<<NV * NC / 4 / 256, 256>>>((const float4*)x, mass, (uint2*)xh, (uint2*)xl);

    // GEMM1: y = coef .* (E^T @ xw), epilogue writes y split
    gemm_kernel<1, 1><<<NV / BM, 256, SMEM_BYTES>>>(Eh, El, xh, xl,
                                                    nullptr, yh, yl, E0, E1);
    // GEMM2: out = E @ y
    gemm_kernel<0, 0><<<NV / BM, 256, SMEM_BYTES>>>(Eh, El, yh, yl,
                                                    out, nullptr, nullptr, nullptr, nullptr);
}